// round 12
// baseline (speedup 1.0000x reference)
#include <cuda_runtime.h>
#include <cuda_bf16.h>
#include <cuda_fp16.h>
#include <cstdint>

#define NB 16
#define NCI 64
#define NCO 128
#define NH 512
#define NW 64
#define CEPS 1e-5f
#define NHW_F 524288.0f   // NB*NH*NW per-channel count

// ---------------- scratch (device globals; no allocations allowed) ----------
__device__ float g_hraw[(size_t)NB * NCO * NH * NW];   // raw conv output, 268MB
__device__ float g_xm[NB * NCO * NH];                  // row means of post-BN1-ReLU
__device__ float g_xn[NB * NCO * NH];                  // layernormed
__device__ float g_f[(size_t)NB * NH * NH];            // softmax(attention)
__device__ float g_zz[NB * NCO * NH];                  // z = Wc @ xn + bc
__device__ float g_y3[NB * NCO * NH];                  // final NL branch
__device__ float g_p1[NB * NCO];                       // per-(b,c) sum of hpost
__device__ float g_p2[NB * NCO];                       // per-(b,c) sum of hpost^2
__device__ float g_s1[NCO];                            // per-channel raw conv sums
__device__ float g_s2[NCO];
__device__ float g_a1[NCO], g_b1v[NCO];                // BN1 scale/shift
__device__ float g_a2[NCO], g_b2v[NCO];                // BN2 scale/shift
__device__ float g_wct[NCO * NCO];                     // (out_w@g_w) transposed [c][o]
__device__ float g_bcv[NCO];                           // out_w@g_b
// fp16 conv weights, pre-swizzled: per chunk (kh*3+kw), tile [co(128) x ci(64)]
__device__ __half g_wA[9 * 8192];

__device__ __forceinline__ float warpsum(float v) {
#pragma unroll
    for (int o = 16; o; o >>= 1) v += __shfl_down_sync(0xffffffffu, v, o);
    return v;
}
__device__ __forceinline__ float warpmax(float v) {
#pragma unroll
    for (int o = 16; o; o >>= 1) v = fmaxf(v, __shfl_xor_sync(0xffffffffu, v, o));
    return v;
}

// =================== mma.sync helpers (baseline PTX, compute_103-safe) ======
__device__ __forceinline__ uint32_t smem_u32(const void* p) {
    uint32_t a;
    asm("{ .reg .u64 t; cvta.to.shared.u64 t, %1; cvt.u32.u64 %0, t; }"
        : "=r"(a) : "l"(p));
    return a;
}
__device__ __forceinline__ void ldsm4(uint32_t* r, uint32_t a) {
    asm volatile("ldmatrix.sync.aligned.m8n8.x4.shared.b16 {%0,%1,%2,%3}, [%4];"
                 : "=r"(r[0]), "=r"(r[1]), "=r"(r[2]), "=r"(r[3]) : "r"(a));
}
__device__ __forceinline__ void mma16816h(float* d, const uint32_t* a, const uint32_t* b) {
    asm volatile("mma.sync.aligned.m16n8k16.row.col.f32.f16.f16.f32 "
                 "{%0,%1,%2,%3}, {%4,%5,%6,%7}, {%8,%9}, {%0,%1,%2,%3};"
                 : "+f"(d[0]), "+f"(d[1]), "+f"(d[2]), "+f"(d[3])
                 : "r"(a[0]), "r"(a[1]), "r"(a[2]), "r"(a[3]),
                   "r"(b[0]), "r"(b[1]));
}
__device__ __forceinline__ void cp16(uint32_t s, const void* g) {
    asm volatile("cp.async.cg.shared.global [%0], [%1], 16;" :: "r"(s), "l"(g));
}
#define CP_COMMIT() asm volatile("cp.async.commit_group;" ::: "memory")
#define CP_WAIT0()  asm volatile("cp.async.wait_group 0;" ::: "memory")

// A tile: rows of 64 fp16 (128B), 16B chunks XOR-swizzled by row&7
__device__ __forceinline__ uint32_t tile_addr(uint32_t base, int row, int kc) {
    return base + row * 128 + ((kc ^ (row & 7)) << 4);
}
// A-operand x4 at (m0, kc16Bchunk)
__device__ __forceinline__ void ld_a(uint32_t* r, uint32_t base, int m0, int kc, int lane) {
    int sel = lane >> 3;
    int rr = m0 + (lane & 7) + ((sel & 1) << 3);
    int cc = kc + (sel >> 1);
    ldsm4(r, tile_addr(base, rr, cc));
}
// B-operand from the extended input tile: pixel n -> (hrow=r+kh, wext=w+kw)
// ext layout: [(hrow*66+wext)][64 ci fp16 = 128B], chunk XOR-swizzled by wext&7
__device__ __forceinline__ void ld_b_ext(uint32_t* r, uint32_t base, int n0, int kc,
                                         int kh, int kw, int lane) {
    int sel = lane >> 3;
    int n = n0 + (lane & 7) + ((sel >> 1) << 3);
    int cc = kc + (sel & 1);
    int hrow = (n >> 6) + kh;
    int wext = (n & 63) + kw;
    uint32_t addr = base + (uint32_t)(hrow * 66 + wext) * 128
                  + (((uint32_t)cc ^ (uint32_t)(wext & 7)) << 4);
    ldsm4(r, addr);
}

// smem layout for conv kernel (dynamic): double-buffered A + single fp16 ext
#define OFF_A0 0
#define OFF_A1 16384
#define OFF_E  32768
#define EXT_PITCH 8448              // 66 * 128 bytes per h-row
#define SMEM_TC (OFF_E + 4 * EXT_PITCH)   // 66560 (65KB)

// ---------------- 0: zero the atomic accumulators ---------------------------
__global__ void k_zero() {
    int t = threadIdx.x;
    if (t < NCO) { g_s1[t] = 0.f; g_s2[t] = 0.f; }
}

// ---------------- 0b: weight prep: fp16, pre-swizzled ------------------------
__global__ void k_wprep(const float* __restrict__ cw) {
    int c9 = blockIdx.x;
    int kh = c9 / 3, kw = c9 % 3;
    for (int i = threadIdx.x; i < 8192; i += 256) {
        int co = i >> 6, ci = i & 63;
        float v = cw[co * 576 + ci * 9 + kh * 3 + kw];
        uint32_t off = (uint32_t)co * 128 + ((((uint32_t)ci >> 3) ^ (co & 7)) << 4)
                     + (ci & 7) * 2;                       // bytes
        g_wA[c9 * 8192 + (off >> 1)] = __float2half(v);
    }
}

// ---------------- 1: conv 3x3 reflect via mma.sync fp16 ---------------------
// grid (256 h-pairs, 16 b), 256 threads = 8 warps (4m x 2n).
// CTA tile: [128 co] x [128 px = 2 h-rows x 64 w]; K = 9 chunks of 64 ci.
__global__ void __launch_bounds__(256) k_conv_mma(const float* __restrict__ x) {
    extern __shared__ char smem[];
    uint32_t sb = smem_u32(smem);
    int t = threadIdx.x, wid = t >> 5, lane = t & 31;
    int h0 = blockIdx.x * 2, b = blockIdx.y;
    int wm = (wid & 3) * 32;      // warp m-base (couts)
    int wn = (wid >> 2) * 64;     // warp n-base (pixels)

    float d[2][8][4];
#pragma unroll
    for (int i = 0; i < 2; i++)
#pragma unroll
        for (int j = 0; j < 8; j++)
#pragma unroll
            for (int q = 0; q < 4; q++) d[i][j][q] = 0.f;

    const float* xb = x + (size_t)b * NCI * NH * NW;

    // ---- prologue: async stage A[0] while we build the ext tile ------------
    {
        const char* src = (const char*)(g_wA + 0);
        for (int i = t; i < 1024; i += 256)
            cp16(sb + OFF_A0 + i * 16, src + i * 16);
        CP_COMMIT();
    }

    // ---- build extended input tile: (hrow 0..3, ci 0..63, wext 0..65) ------
    for (int p = wid; p < 256; p += 8) {
        int hrow = p >> 6, ci = p & 63;
        int row = h0 + hrow - 1;
        row = (row < 0) ? 1 : ((row > NH - 1) ? NH - 2 : row);
        const float* xr = xb + ((size_t)ci * NH + row) * NW;
        uint32_t rowoff = (uint32_t)(hrow * 66) * 128;
        int ci8 = ci >> 3, cib = (ci & 7) * 2;
#pragma unroll
        for (int rep = 0; rep < 3; rep++) {
            int wext = lane + rep * 32;
            if (rep == 2 && lane >= 2) break;
            if (rep == 2) wext = 64 + lane;
            int ws = wext - 1;
            ws = (ws < 0) ? 1 : ((ws > NW - 1) ? NW - 2 : ws);
            float v = xr[ws];
            uint32_t off = rowoff + (uint32_t)wext * 128
                         + (((uint32_t)ci8 ^ (uint32_t)(wext & 7)) << 4) + cib;
            *(__half*)(smem + OFF_E + off) = __float2half(v);
        }
    }

    // ---- mainloop over 9 (kh,kw) chunks, A double-buffered -----------------
    for (int c9 = 0; c9 < 9; ++c9) {
        int kh = c9 / 3, kw = c9 - kh * 3;
        uint32_t abase = sb + ((c9 & 1) ? OFF_A1 : OFF_A0);
        CP_WAIT0();          // A[c9] arrived (only outstanding group)
        __syncthreads();     // + ext visible (first iter); all warps past c9-1
        if (c9 < 8) {        // prefetch A[c9+1] into the other buffer
            uint32_t nb = sb + (((c9 + 1) & 1) ? OFF_A1 : OFF_A0);
            const char* src = (const char*)(g_wA + (c9 + 1) * 8192);
            for (int i = t; i < 1024; i += 256)
                cp16(nb + i * 16, src + i * 16);
            CP_COMMIT();
        }
#pragma unroll
        for (int ks = 0; ks < 4; ks++) {
            int kc = ks * 2;
            uint32_t ah[2][4];
            ld_a(ah[0], abase, wm,      kc, lane);
            ld_a(ah[1], abase, wm + 16, kc, lane);
#pragma unroll
            for (int j = 0; j < 4; j++) {
                uint32_t bh[4];
                ld_b_ext(bh, sb + OFF_E, wn + j * 16, kc, kh, kw, lane);
#pragma unroll
                for (int mf = 0; mf < 2; mf++) {
                    mma16816h(d[mf][2 * j],     ah[mf], bh);
                    mma16816h(d[mf][2 * j + 1], ah[mf], bh + 2);
                }
            }
        }
    }

    // ---- epilogue: store D frags (fp32) + BN1 stats ------------------------
    float s1a[4] = {0.f, 0.f, 0.f, 0.f}, s2a[4] = {0.f, 0.f, 0.f, 0.f};
#pragma unroll
    for (int mf = 0; mf < 2; mf++)
#pragma unroll
        for (int half = 0; half < 2; half++) {
            int co = wm + mf * 16 + (lane >> 2) + half * 8;
            int slot = mf * 2 + half;
            size_t cobase = ((size_t)(b * NCO + co) * NH + h0) * NW;
#pragma unroll
            for (int nf = 0; nf < 8; nf++) {
                int n = wn + nf * 8 + (lane & 3) * 2;
                int r = n >> 6, w = n & 63;
                float v0 = d[mf][nf][half * 2 + 0];
                float v1 = d[mf][nf][half * 2 + 1];
                float2 st; st.x = v0; st.y = v1;
                *(float2*)&g_hraw[cobase + (size_t)r * NW + w] = st;
                s1a[slot] += v0 + v1;
                s2a[slot] += v0 * v0 + v1 * v1;
            }
        }
#pragma unroll
    for (int s = 0; s < 4; s++) {
        s1a[s] += __shfl_xor_sync(0xffffffffu, s1a[s], 1);
        s1a[s] += __shfl_xor_sync(0xffffffffu, s1a[s], 2);
        s2a[s] += __shfl_xor_sync(0xffffffffu, s2a[s], 1);
        s2a[s] += __shfl_xor_sync(0xffffffffu, s2a[s], 2);
    }
    if ((lane & 3) == 0) {
#pragma unroll
        for (int s = 0; s < 4; s++) {
            int co = wm + (s >> 1) * 16 + (lane >> 2) + (s & 1) * 8;
            atomicAdd(&g_s1[co], s1a[s]);
            atomicAdd(&g_s2[co], s2a[s]);
        }
    }
}

// ---------------- 2: finalize BN1 scale/shift -------------------------------
__global__ void k_bn1fin(const float* __restrict__ g1, const float* __restrict__ b1) {
    int c = threadIdx.x;
    if (c < NCO) {
        float mean = g_s1[c] * (1.f / NHW_F);
        float var  = g_s2[c] * (1.f / NHW_F) - mean * mean;
        float a = g1[c] * rsqrtf(var + CEPS);
        g_a1[c] = a;
        g_b1v[c] = b1[c] - mean * a;
    }
}

// ---------------- 3: apply BN1+ReLU, row means over W, Σh/Σh² partials ------
// grid: 2048 = (b,c). 256 threads; half-warp (16 lanes x float4) per h-row,
// 32 independent iterations (unroll 4) -> high MLP; 4 shfls per row-sum.
__global__ void __launch_bounds__(256) k_bnrelu_xm() {
    int bc = blockIdx.x;
    int c = bc & 127;
    int t = threadIdx.x, lane = t & 31, wid = t >> 5;
    float a1 = g_a1[c], b1 = g_b1v[c];
    const float4* src = (const float4*)(g_hraw + (size_t)bc * NH * NW); // 16/row
    float p1 = 0.f, p2 = 0.f;
#pragma unroll 4
    for (int it = 0; it < 32; ++it) {
        int row = it * 16 + wid * 2 + (lane >> 4);
        float4 v = src[row * 16 + (lane & 15)];
        float v0 = fmaxf(fmaf(v.x, a1, b1), 0.f);
        float v1 = fmaxf(fmaf(v.y, a1, b1), 0.f);
        float v2 = fmaxf(fmaf(v.z, a1, b1), 0.f);
        float v3 = fmaxf(fmaf(v.w, a1, b1), 0.f);
        float s = v0 + v1 + v2 + v3;
        p1 += s;
        p2 += v0 * v0 + v1 * v1 + v2 * v2 + v3 * v3;
        s += __shfl_xor_sync(0xffffffffu, s, 1);
        s += __shfl_xor_sync(0xffffffffu, s, 2);
        s += __shfl_xor_sync(0xffffffffu, s, 4);
        s += __shfl_xor_sync(0xffffffffu, s, 8);
        if ((lane & 15) == 0) g_xm[(size_t)bc * NH + row] = s * (1.f / 64.f);
    }
    __shared__ float r1[8], r2[8];
    p1 = warpsum(p1); p2 = warpsum(p2);
    if (lane == 0) { r1[wid] = p1; r2[wid] = p2; }
    __syncthreads();
    if (t == 0) {
        float a = 0.f, b2 = 0.f;
#pragma unroll
        for (int i = 0; i < 8; i++) { a += r1[i]; b2 += r2[i]; }
        g_p1[bc] = a; g_p2[bc] = b2;
    }
}

// ---------------- 4: layernorm over (C,H) per batch -------------------------
__global__ void __launch_bounds__(256) k_ln() {
    int b = blockIdx.x;
    const float* xm = g_xm + b * (NCO * NH);
    float* xn = g_xn + b * (NCO * NH);
    int t = threadIdx.x, lane = t & 31, wid = t >> 5;
    float s = 0.f, s2 = 0.f;
    for (int i = t; i < NCO * NH; i += 256) { float v = xm[i]; s += v; s2 += v * v; }
    __shared__ float rb[16];
    __shared__ float st[2];
    s = warpsum(s); s2 = warpsum(s2);
    if (lane == 0) { rb[wid] = s; rb[8 + wid] = s2; }
    __syncthreads();
    if (t == 0) {
        float a = 0.f, b2 = 0.f;
#pragma unroll
        for (int i = 0; i < 8; i++) { a += rb[i]; b2 += rb[8 + i]; }
        float mu = a * (1.f / 65536.f);
        float var = b2 * (1.f / 65536.f) - mu * mu;
        st[0] = mu; st[1] = rsqrtf(var + CEPS);
    }
    __syncthreads();
    float mu = st[0], rs = st[1];
    for (int i = t; i < NCO * NH; i += 256) xn[i] = (xm[i] - mu) * rs;
}

// ---------------- 5: Wc = out_w @ g_w (stored transposed), bc = out_w @ g_b -
__global__ void k_wc(const float* __restrict__ ow, const float* __restrict__ gw,
                     const float* __restrict__ gb) {
    int o = blockIdx.x, c = threadIdx.x;
    float s = 0.f;
    for (int m = 0; m < NCO; m++) s = fmaf(ow[o * NCO + m], gw[m * NCO + c], s);
    g_wct[c * NCO + o] = s;
    if (c == 0) {
        float bb = 0.f;
        for (int m = 0; m < NCO; m++) bb = fmaf(ow[o * NCO + m], gb[m], bb);
        g_bcv[o] = bb;
    }
}

// ---------------- 6: z[b,o,k] = Σc Wc[o,c]*xn[b,c,k] + bc[o] ----------------
__global__ void __launch_bounds__(256) k_z() {
    __shared__ float xs[NCO * 64];
    int k0 = blockIdx.x * 64, b = blockIdx.y;
    int t = threadIdx.x;
    for (int i = t; i < NCO * 64; i += 256) {
        int c = i >> 6, kk = i & 63;
        xs[i] = g_xn[((b << 7) + c) * NH + k0 + kk];
    }
    __syncthreads();
    int kk = t & 63, og = t >> 6;
    float acc[32];
#pragma unroll
    for (int i = 0; i < 32; i++) acc[i] = 0.f;
    for (int c = 0; c < NCO; c++) {
        float xv = xs[c * 64 + kk];
        const float4* wr = (const float4*)(g_wct + c * NCO + og * 32);
#pragma unroll
        for (int i4 = 0; i4 < 8; i4++) {
            float4 wv = __ldg(wr + i4);
            acc[i4 * 4 + 0] = fmaf(wv.x, xv, acc[i4 * 4 + 0]);
            acc[i4 * 4 + 1] = fmaf(wv.y, xv, acc[i4 * 4 + 1]);
            acc[i4 * 4 + 2] = fmaf(wv.z, xv, acc[i4 * 4 + 2]);
            acc[i4 * 4 + 3] = fmaf(wv.w, xv, acc[i4 * 4 + 3]);
        }
    }
#pragma unroll
    for (int i = 0; i < 32; i++) {
        int o = og * 32 + i;
        g_zz[((b << 7) + o) * NH + k0 + kk] = acc[i] + g_bcv[o];
    }
}

// ---------------- 7: S = xn^T xn / sqrt(C)  [b,h,k] -------------------------
__global__ void __launch_bounds__(256) k_sgemm() {
    __shared__ float As[64 * 64], Bs[64 * 64];
    int k0 = blockIdx.x * 64, h0 = blockIdx.y * 64, b = blockIdx.z;
    int t = threadIdx.x, tx = t & 15, ty = t >> 4;
    float acc[4][4];
#pragma unroll
    for (int i = 0; i < 4; i++)
#pragma unroll
        for (int j = 0; j < 4; j++) acc[i][j] = 0.f;
    for (int cc = 0; cc < 2; ++cc) {
        int c0 = cc * 64;
        for (int i = t; i < 4096; i += 256) {
            int c = i >> 6, j = i & 63;
            As[i] = g_xn[((b << 7) + c0 + c) * NH + h0 + j];
            Bs[i] = g_xn[((b << 7) + c0 + c) * NH + k0 + j];
        }
        __syncthreads();
#pragma unroll 8
        for (int c = 0; c < 64; c++) {
            float4 av = *(const float4*)&As[c * 64 + ty * 4];
            float4 bv = *(const float4*)&Bs[c * 64 + tx * 4];
            float a[4] = {av.x, av.y, av.z, av.w};
            float bb[4] = {bv.x, bv.y, bv.z, bv.w};
#pragma unroll
            for (int i = 0; i < 4; i++)
#pragma unroll
                for (int j = 0; j < 4; j++) acc[i][j] = fmaf(a[i], bb[j], acc[i][j]);
        }
        __syncthreads();
    }
    const float SC = 0.08838834764831845f;  // 1/sqrt(128)
#pragma unroll
    for (int i = 0; i < 4; i++) {
        float4 v;
        v.x = acc[i][0] * SC; v.y = acc[i][1] * SC;
        v.z = acc[i][2] * SC; v.w = acc[i][3] * SC;
        *(float4*)&g_f[((size_t)(b << 9) + h0 + ty * 4 + i) * NH + k0 + tx * 4] = v;
    }
}

// ---------------- 8: row softmax over k (512) -------------------------------
__global__ void __launch_bounds__(128) k_softmax() {
    size_t row = blockIdx.x;
    float4* p = (float4*)(g_f + row * NH);
    int t = threadIdx.x, lane = t & 31, wid = t >> 5;
    __shared__ float sb[4];
    float4 v = p[t];
    float m = fmaxf(fmaxf(v.x, v.y), fmaxf(v.z, v.w));
    m = warpmax(m);
    if (lane == 0) sb[wid] = m;
    __syncthreads();
    m = fmaxf(fmaxf(sb[0], sb[1]), fmaxf(sb[2], sb[3]));
    float e0 = expf(v.x - m), e1 = expf(v.y - m), e2 = expf(v.z - m), e3 = expf(v.w - m);
    float s = e0 + e1 + e2 + e3;
    s = warpsum(s);
    __syncthreads();
    if (lane == 0) sb[wid] = s;
    __syncthreads();
    float inv = 1.f / (sb[0] + sb[1] + sb[2] + sb[3]);
    float4 o; o.x = e0 * inv; o.y = e1 * inv; o.z = e2 * inv; o.w = e3 * inv;
    p[t] = o;
}

// ---------------- 9: y3[b,o,h] = Σk f[b,h,k] z[b,o,k] + out_b[o] ------------
__global__ void __launch_bounds__(256) k_y3(const float* __restrict__ outb) {
    __shared__ float fs[64 * 35];
    __shared__ float zs[NCO * 32];
    int h0 = blockIdx.x * 64, b = blockIdx.y;
    int t = threadIdx.x, hx = t & 15, og = t >> 4;
    float acc[4][8];
#pragma unroll
    for (int j = 0; j < 4; j++)
#pragma unroll
        for (int i = 0; i < 8; i++) acc[j][i] = 0.f;
    for (int kt = 0; kt < 16; ++kt) {
        int k0 = kt * 32;
        for (int i = t; i < 2048; i += 256) {
            int hh = i >> 5, kk = i & 31;
            fs[hh * 35 + kk] = g_f[((size_t)(b << 9) + h0 + hh) * NH + k0 + kk];
        }
        for (int i = t; i < 4096; i += 256) {
            int o = i >> 5, kk = i & 31;
            zs[i] = g_zz[((b << 7) + o) * NH + k0 + kk];
        }
        __syncthreads();
#pragma unroll 4
        for (int kk = 0; kk < 32; kk++) {
            float fv[4], zv[8];
#pragma unroll
            for (int j = 0; j < 4; j++) fv[j] = fs[(hx * 4 + j) * 35 + kk];
#pragma unroll
            for (int i = 0; i < 8; i++) zv[i] = zs[(og * 8 + i) * 32 + kk];
#pragma unroll
            for (int j = 0; j < 4; j++)
#pragma unroll
                for (int i = 0; i < 8; i++) acc[j][i] = fmaf(fv[j], zv[i], acc[j][i]);
        }
        __syncthreads();
    }
#pragma unroll
    for (int i = 0; i < 8; i++) {
        int o = og * 8 + i;
        float ob = outb[o];
#pragma unroll
        for (int j = 0; j < 4; j++)
            g_y3[((b << 7) + o) * NH + h0 + hx * 4 + j] = acc[j][i] + ob;
    }
}

// ---------------- 10: BN2 stats from small tensors --------------------------
__global__ void __launch_bounds__(256) k_bn2red(const float* __restrict__ g2,
                                                const float* __restrict__ b2p) {
    int c = blockIdx.x;
    int t = threadIdx.x, lane = t & 31, wid = t >> 5;
    float sy = 0.f, sy2 = 0.f, sxy = 0.f;
    for (int i = t; i < NB * NH; i += 256) {
        int b = i >> 9, h = i & 511;
        size_t idx = (size_t)((b << 7) + c) * NH + h;
        float y = g_y3[idx], xm = g_xm[idx];
        sy += y; sy2 += y * y; sxy += y * xm;
    }
    float sp1 = 0.f, sp2 = 0.f;
    if (t < NB) { sp1 = g_p1[t * NCO + c]; sp2 = g_p2[t * NCO + c]; }
    __shared__ float rb[5][8];
    sy = warpsum(sy); sy2 = warpsum(sy2); sxy = warpsum(sxy);
    sp1 = warpsum(sp1); sp2 = warpsum(sp2);
    if (lane == 0) { rb[0][wid]=sy; rb[1][wid]=sy2; rb[2][wid]=sxy; rb[3][wid]=sp1; rb[4][wid]=sp2; }
    __syncthreads();
    if (t == 0) {
        float SY=0, SY2=0, SXY=0, P1=0, P2=0;
#pragma unroll
        for (int i = 0; i < 8; i++) { SY+=rb[0][i]; SY2+=rb[1][i]; SXY+=rb[2][i]; P1+=rb[3][i]; P2+=rb[4][i]; }
        float S1 = P1 + 64.f * SY;
        float S2 = P2 + 128.f * SXY + 64.f * SY2;
        float mean = S1 * (1.f / NHW_F);
        float var  = S2 * (1.f / NHW_F) - mean * mean;
        float a = g2[c] * rsqrtf(var + CEPS);
        g_a2[c] = a;
        g_b2v[c] = b2p[c] - mean * a;
    }
}

// ---------------- 11: fused epilogue: BN1+ReLU + add y + BN2 + SiLU ---------
// 8 fp32 elems/thread (two independent float4 loads -> MLP 2/thread),
// all within one h-row -> one y3 read.
__global__ void __launch_bounds__(256) k_final(float* __restrict__ out) {
    size_t gi = (size_t)blockIdx.x * 256 + threadIdx.x;
    size_t base = gi * 8;
    size_t row = base >> 6;                               // (b*128+c)*512+h
    int c = (int)((row >> 9) & 127);
    float a1 = g_a1[c], b1 = g_b1v[c], a2 = g_a2[c], b2 = g_b2v[c];
    float yv = g_y3[row];
    float4 v0 = *(const float4*)(g_hraw + base);
    float4 v1 = *(const float4*)(g_hraw + base + 4);
    float in[8] = {v0.x, v0.y, v0.z, v0.w, v1.x, v1.y, v1.z, v1.w};
    float r[8];
#pragma unroll
    for (int i = 0; i < 8; i++) {
        float hp = fmaxf(fmaf(in[i], a1, b1), 0.f);
        float q = fmaf(hp + yv, a2, b2);
        r[i] = q * (1.f / (1.f + expf(-q)));
    }
    float4 o0; o0.x = r[0]; o0.y = r[1]; o0.z = r[2]; o0.w = r[3];
    float4 o1; o1.x = r[4]; o1.y = r[5]; o1.z = r[6]; o1.w = r[7];
    *(float4*)(out + base) = o0;
    *(float4*)(out + base + 4) = o1;
}

// ---------------- launch ----------------------------------------------------
extern "C" void kernel_launch(void* const* d_in, const int* in_sizes, int n_in,
                              void* d_out, int out_size) {
    const float* x      = (const float*)d_in[0];
    const float* conv_w = (const float*)d_in[1];
    const float* bn1_g  = (const float*)d_in[2];
    const float* bn1_b  = (const float*)d_in[3];
    const float* gw     = (const float*)d_in[4];
    const float* gb     = (const float*)d_in[5];
    const float* ow     = (const float*)d_in[6];
    const float* ob     = (const float*)d_in[7];
    const float* bn2_g  = (const float*)d_in[8];
    const float* bn2_b  = (const float*)d_in[9];
    float* out = (float*)d_out;

    static int smem_set = 0;
    if (!smem_set) {
        cudaFuncSetAttribute(k_conv_mma, cudaFuncAttributeMaxDynamicSharedMemorySize, SMEM_TC);
        smem_set = 1;
    }

    k_zero<<<1, 256>>>();
    k_wprep<<<9, 256>>>(conv_w);
    k_conv_mma<<<dim3(NH / 2, NB), 256, SMEM_TC>>>(x);
    k_bn1fin<<<1, 128>>>(bn1_g, bn1_b);
    k_bnrelu_xm<<<NB * NCO, 256>>>();
    k_ln<<<NB, 256>>>();
    k_wc<<<NCO, NCO>>>(ow, gw, gb);
    k_z<<<dim3(8, NB), 256>>>();
    k_sgemm<<<dim3(8, 8, NB), 256>>>();
    k_softmax<<<NB * NH, 128>>>();
    k_y3<<<dim3(8, NB), 256>>>(ob);
    k_bn2red<<<NCO, 256>>>(bn2_g, bn2_b);
    k_final<<<65536 / 2, 256>>>(out);
}

// round 13
// speedup vs baseline: 1.3009x; 1.3009x over previous
#include <cuda_runtime.h>
#include <cuda_bf16.h>
#include <cuda_fp16.h>
#include <cstdint>

#define NB 16
#define NCI 64
#define NCO 128
#define NH 512
#define NW 64
#define CEPS 1e-5f
#define NHW_F 524288.0f   // NB*NH*NW per-channel count

// ---------------- scratch (device globals; no allocations allowed) ----------
__device__ float g_hraw[(size_t)NB * NCO * NH * NW];   // raw conv output, 268MB
__device__ float g_xm[NB * NCO * NH];                  // row means of post-BN1-ReLU
__device__ float g_xn[NB * NCO * NH];                  // layernormed
__device__ float g_f[(size_t)NB * NH * NH];            // softmax(attention)
__device__ float g_zz[NB * NCO * NH];                  // z = Wc @ xn + bc
__device__ float g_y3[NB * NCO * NH];                  // final NL branch
__device__ float g_p1[NB * NCO];                       // per-(b,c) sum of hpost
__device__ float g_p2[NB * NCO];                       // per-(b,c) sum of hpost^2
__device__ float g_s1[NCO];                            // per-channel raw conv sums
__device__ float g_s2[NCO];
__device__ float g_a1[NCO], g_b1v[NCO];                // BN1 scale/shift
__device__ float g_a2[NCO], g_b2v[NCO];                // BN2 scale/shift
__device__ float g_wct[NCO * NCO];                     // (out_w@g_w) transposed [c][o]
__device__ float g_bcv[NCO];                           // out_w@g_b
// fp16 conv weights, pre-swizzled: per chunk (kh*3+kw), tile [co(128) x ci(64)]
__device__ __half g_wA[9 * 8192];

__device__ __forceinline__ float warpsum(float v) {
#pragma unroll
    for (int o = 16; o; o >>= 1) v += __shfl_down_sync(0xffffffffu, v, o);
    return v;
}
__device__ __forceinline__ float warpmax(float v) {
#pragma unroll
    for (int o = 16; o; o >>= 1) v = fmaxf(v, __shfl_xor_sync(0xffffffffu, v, o));
    return v;
}

// =================== mma.sync helpers (baseline PTX, compute_103-safe) ======
__device__ __forceinline__ uint32_t smem_u32(const void* p) {
    uint32_t a;
    asm("{ .reg .u64 t; cvta.to.shared.u64 t, %1; cvt.u32.u64 %0, t; }"
        : "=r"(a) : "l"(p));
    return a;
}
__device__ __forceinline__ void ldsm4(uint32_t* r, uint32_t a) {
    asm volatile("ldmatrix.sync.aligned.m8n8.x4.shared.b16 {%0,%1,%2,%3}, [%4];"
                 : "=r"(r[0]), "=r"(r[1]), "=r"(r[2]), "=r"(r[3]) : "r"(a));
}
__device__ __forceinline__ void mma16816h(float* d, const uint32_t* a, const uint32_t* b) {
    asm volatile("mma.sync.aligned.m16n8k16.row.col.f32.f16.f16.f32 "
                 "{%0,%1,%2,%3}, {%4,%5,%6,%7}, {%8,%9}, {%0,%1,%2,%3};"
                 : "+f"(d[0]), "+f"(d[1]), "+f"(d[2]), "+f"(d[3])
                 : "r"(a[0]), "r"(a[1]), "r"(a[2]), "r"(a[3]),
                   "r"(b[0]), "r"(b[1]));
}
__device__ __forceinline__ void cp16(uint32_t s, const void* g) {
    asm volatile("cp.async.cg.shared.global [%0], [%1], 16;" :: "r"(s), "l"(g));
}
#define CP_COMMIT() asm volatile("cp.async.commit_group;" ::: "memory")
#define CP_WAIT0()  asm volatile("cp.async.wait_group 0;" ::: "memory")

// A tile: rows of 64 fp16 (128B), 16B chunks XOR-swizzled by row&7
__device__ __forceinline__ uint32_t tile_addr(uint32_t base, int row, int kc) {
    return base + row * 128 + ((kc ^ (row & 7)) << 4);
}
// A-operand x4 at (m0, kc16Bchunk)
__device__ __forceinline__ void ld_a(uint32_t* r, uint32_t base, int m0, int kc, int lane) {
    int sel = lane >> 3;
    int rr = m0 + (lane & 7) + ((sel & 1) << 3);
    int cc = kc + (sel >> 1);
    ldsm4(r, tile_addr(base, rr, cc));
}
// B-operand from the extended input tile: pixel n -> (hrow=r+kh, wext=w+kw)
// ext layout: [(hrow*66+wext)][64 ci fp16 = 128B], chunk XOR-swizzled by wext&7
__device__ __forceinline__ void ld_b_ext(uint32_t* r, uint32_t base, int n0, int kc,
                                         int kh, int kw, int lane) {
    int sel = lane >> 3;
    int n = n0 + (lane & 7) + ((sel >> 1) << 3);
    int cc = kc + (sel & 1);
    int hrow = (n >> 6) + kh;
    int wext = (n & 63) + kw;
    uint32_t addr = base + (uint32_t)(hrow * 66 + wext) * 128
                  + (((uint32_t)cc ^ (uint32_t)(wext & 7)) << 4);
    ldsm4(r, addr);
}

// smem layout for conv kernel (dynamic): double-buffered A + single fp16 ext
#define OFF_A0 0
#define OFF_A1 16384
#define OFF_E  32768
#define EXT_PITCH 8448              // 66 * 128 bytes per h-row
#define SMEM_TC (OFF_E + 4 * EXT_PITCH)   // 66560 (65KB)

// ---------------- 0: zero the atomic accumulators ---------------------------
__global__ void k_zero() {
    int t = threadIdx.x;
    if (t < NCO) { g_s1[t] = 0.f; g_s2[t] = 0.f; }
}

// ---------------- 0b: weight prep: fp16, pre-swizzled ------------------------
__global__ void k_wprep(const float* __restrict__ cw) {
    int c9 = blockIdx.x;
    int kh = c9 / 3, kw = c9 % 3;
    for (int i = threadIdx.x; i < 8192; i += 256) {
        int co = i >> 6, ci = i & 63;
        float v = cw[co * 576 + ci * 9 + kh * 3 + kw];
        uint32_t off = (uint32_t)co * 128 + ((((uint32_t)ci >> 3) ^ (co & 7)) << 4)
                     + (ci & 7) * 2;                       // bytes
        g_wA[c9 * 8192 + (off >> 1)] = __float2half(v);
    }
}

// ---------------- 1: conv 3x3 reflect via mma.sync fp16 ---------------------
// grid (256 h-pairs, 16 b), 256 threads = 8 warps (4m x 2n).
// CTA tile: [128 co] x [128 px = 2 h-rows x 64 w]; K = 9 chunks of 64 ci.
__global__ void __launch_bounds__(256) k_conv_mma(const float* __restrict__ x) {
    extern __shared__ char smem[];
    uint32_t sb = smem_u32(smem);
    int t = threadIdx.x, wid = t >> 5, lane = t & 31;
    int h0 = blockIdx.x * 2, b = blockIdx.y;
    int wm = (wid & 3) * 32;      // warp m-base (couts)
    int wn = (wid >> 2) * 64;     // warp n-base (pixels)

    float d[2][8][4];
#pragma unroll
    for (int i = 0; i < 2; i++)
#pragma unroll
        for (int j = 0; j < 8; j++)
#pragma unroll
            for (int q = 0; q < 4; q++) d[i][j][q] = 0.f;

    const float* xb = x + (size_t)b * NCI * NH * NW;

    // ---- prologue: async stage A[0] while we build the ext tile ------------
    {
        const char* src = (const char*)(g_wA + 0);
        for (int i = t; i < 1024; i += 256)
            cp16(sb + OFF_A0 + i * 16, src + i * 16);
        CP_COMMIT();
    }

    // ---- build extended input tile: (hrow 0..3, ci 0..63, wext 0..65) ------
    for (int p = wid; p < 256; p += 8) {
        int hrow = p >> 6, ci = p & 63;
        int row = h0 + hrow - 1;
        row = (row < 0) ? 1 : ((row > NH - 1) ? NH - 2 : row);
        const float* xr = xb + ((size_t)ci * NH + row) * NW;
        uint32_t rowoff = (uint32_t)(hrow * 66) * 128;
        int ci8 = ci >> 3, cib = (ci & 7) * 2;
#pragma unroll
        for (int rep = 0; rep < 3; rep++) {
            int wext = lane + rep * 32;
            if (rep == 2 && lane >= 2) break;
            if (rep == 2) wext = 64 + lane;
            int ws = wext - 1;
            ws = (ws < 0) ? 1 : ((ws > NW - 1) ? NW - 2 : ws);
            float v = xr[ws];
            uint32_t off = rowoff + (uint32_t)wext * 128
                         + (((uint32_t)ci8 ^ (uint32_t)(wext & 7)) << 4) + cib;
            *(__half*)(smem + OFF_E + off) = __float2half(v);
        }
    }

    // ---- mainloop over 9 (kh,kw) chunks, A double-buffered -----------------
    for (int c9 = 0; c9 < 9; ++c9) {
        int kh = c9 / 3, kw = c9 - kh * 3;
        uint32_t abase = sb + ((c9 & 1) ? OFF_A1 : OFF_A0);
        CP_WAIT0();          // A[c9] arrived (only outstanding group)
        __syncthreads();     // + ext visible (first iter); all warps past c9-1
        if (c9 < 8) {        // prefetch A[c9+1] into the other buffer
            uint32_t nb = sb + (((c9 + 1) & 1) ? OFF_A1 : OFF_A0);
            const char* src = (const char*)(g_wA + (c9 + 1) * 8192);
            for (int i = t; i < 1024; i += 256)
                cp16(nb + i * 16, src + i * 16);
            CP_COMMIT();
        }
#pragma unroll
        for (int ks = 0; ks < 4; ks++) {
            int kc = ks * 2;
            uint32_t ah[2][4];
            ld_a(ah[0], abase, wm,      kc, lane);
            ld_a(ah[1], abase, wm + 16, kc, lane);
#pragma unroll
            for (int j = 0; j < 4; j++) {
                uint32_t bh[4];
                ld_b_ext(bh, sb + OFF_E, wn + j * 16, kc, kh, kw, lane);
#pragma unroll
                for (int mf = 0; mf < 2; mf++) {
                    mma16816h(d[mf][2 * j],     ah[mf], bh);
                    mma16816h(d[mf][2 * j + 1], ah[mf], bh + 2);
                }
            }
        }
    }

    // ---- epilogue: store D frags (fp32) + BN1 stats ------------------------
    float s1a[4] = {0.f, 0.f, 0.f, 0.f}, s2a[4] = {0.f, 0.f, 0.f, 0.f};
#pragma unroll
    for (int mf = 0; mf < 2; mf++)
#pragma unroll
        for (int half = 0; half < 2; half++) {
            int co = wm + mf * 16 + (lane >> 2) + half * 8;
            int slot = mf * 2 + half;
            size_t cobase = ((size_t)(b * NCO + co) * NH + h0) * NW;
#pragma unroll
            for (int nf = 0; nf < 8; nf++) {
                int n = wn + nf * 8 + (lane & 3) * 2;
                int r = n >> 6, w = n & 63;
                float v0 = d[mf][nf][half * 2 + 0];
                float v1 = d[mf][nf][half * 2 + 1];
                float2 st; st.x = v0; st.y = v1;
                *(float2*)&g_hraw[cobase + (size_t)r * NW + w] = st;
                s1a[slot] += v0 + v1;
                s2a[slot] += v0 * v0 + v1 * v1;
            }
        }
#pragma unroll
    for (int s = 0; s < 4; s++) {
        s1a[s] += __shfl_xor_sync(0xffffffffu, s1a[s], 1);
        s1a[s] += __shfl_xor_sync(0xffffffffu, s1a[s], 2);
        s2a[s] += __shfl_xor_sync(0xffffffffu, s2a[s], 1);
        s2a[s] += __shfl_xor_sync(0xffffffffu, s2a[s], 2);
    }
    if ((lane & 3) == 0) {
#pragma unroll
        for (int s = 0; s < 4; s++) {
            int co = wm + (s >> 1) * 16 + (lane >> 2) + (s & 1) * 8;
            atomicAdd(&g_s1[co], s1a[s]);
            atomicAdd(&g_s2[co], s2a[s]);
        }
    }
}

// ---------------- 2: finalize BN1 scale/shift -------------------------------
__global__ void k_bn1fin(const float* __restrict__ g1, const float* __restrict__ b1) {
    int c = threadIdx.x;
    if (c < NCO) {
        float mean = g_s1[c] * (1.f / NHW_F);
        float var  = g_s2[c] * (1.f / NHW_F) - mean * mean;
        float a = g1[c] * rsqrtf(var + CEPS);
        g_a1[c] = a;
        g_b1v[c] = b1[c] - mean * a;
    }
}

// ---------------- 3: apply BN1+ReLU, row means over W, Σh/Σh² partials ------
// grid: 2048 = (b,c). 256 threads = 8 warps, warp owns one h row per iter.
__global__ void __launch_bounds__(256) k_bnrelu_xm() {
    int bc = blockIdx.x;
    int c = bc & 127;
    int t = threadIdx.x, lane = t & 31, wid = t >> 5;
    float a1 = g_a1[c], b1 = g_b1v[c];
    const float2* src = (const float2*)(g_hraw + (size_t)bc * NH * NW);
    float p1 = 0.f, p2 = 0.f;
    for (int it = 0; it < 64; ++it) {
        int h = it * 8 + wid;
        float2 v = src[h * 32 + lane];
        float v0 = fmaxf(fmaf(v.x, a1, b1), 0.f);
        float v1 = fmaxf(fmaf(v.y, a1, b1), 0.f);
        float s = v0 + v1;
        p1 += s;
        p2 += v0 * v0 + v1 * v1;
        s = warpsum(s);
        if (lane == 0) g_xm[(size_t)bc * NH + h] = s * (1.f / 64.f);
    }
    __shared__ float r1[8], r2[8];
    p1 = warpsum(p1); p2 = warpsum(p2);
    if (lane == 0) { r1[wid] = p1; r2[wid] = p2; }
    __syncthreads();
    if (t == 0) {
        float a = 0.f, b2 = 0.f;
#pragma unroll
        for (int i = 0; i < 8; i++) { a += r1[i]; b2 += r2[i]; }
        g_p1[bc] = a; g_p2[bc] = b2;
    }
}

// ---------------- 4: layernorm over (C,H) per batch -------------------------
__global__ void __launch_bounds__(256) k_ln() {
    int b = blockIdx.x;
    const float* xm = g_xm + b * (NCO * NH);
    float* xn = g_xn + b * (NCO * NH);
    int t = threadIdx.x, lane = t & 31, wid = t >> 5;
    float s = 0.f, s2 = 0.f;
    for (int i = t; i < NCO * NH; i += 256) { float v = xm[i]; s += v; s2 += v * v; }
    __shared__ float rb[16];
    __shared__ float st[2];
    s = warpsum(s); s2 = warpsum(s2);
    if (lane == 0) { rb[wid] = s; rb[8 + wid] = s2; }
    __syncthreads();
    if (t == 0) {
        float a = 0.f, b2 = 0.f;
#pragma unroll
        for (int i = 0; i < 8; i++) { a += rb[i]; b2 += rb[8 + i]; }
        float mu = a * (1.f / 65536.f);
        float var = b2 * (1.f / 65536.f) - mu * mu;
        st[0] = mu; st[1] = rsqrtf(var + CEPS);
    }
    __syncthreads();
    float mu = st[0], rs = st[1];
    for (int i = t; i < NCO * NH; i += 256) xn[i] = (xm[i] - mu) * rs;
}

// ---------------- 5: Wc = out_w @ g_w (stored transposed), bc = out_w @ g_b -
__global__ void k_wc(const float* __restrict__ ow, const float* __restrict__ gw,
                     const float* __restrict__ gb) {
    int o = blockIdx.x, c = threadIdx.x;
    float s = 0.f;
    for (int m = 0; m < NCO; m++) s = fmaf(ow[o * NCO + m], gw[m * NCO + c], s);
    g_wct[c * NCO + o] = s;
    if (c == 0) {
        float bb = 0.f;
        for (int m = 0; m < NCO; m++) bb = fmaf(ow[o * NCO + m], gb[m], bb);
        g_bcv[o] = bb;
    }
}

// ---------------- 6: z[b,o,k] = Σc Wc[o,c]*xn[b,c,k] + bc[o] ----------------
__global__ void __launch_bounds__(256) k_z() {
    __shared__ float xs[NCO * 64];
    int k0 = blockIdx.x * 64, b = blockIdx.y;
    int t = threadIdx.x;
    for (int i = t; i < NCO * 64; i += 256) {
        int c = i >> 6, kk = i & 63;
        xs[i] = g_xn[((b << 7) + c) * NH + k0 + kk];
    }
    __syncthreads();
    int kk = t & 63, og = t >> 6;
    float acc[32];
#pragma unroll
    for (int i = 0; i < 32; i++) acc[i] = 0.f;
    for (int c = 0; c < NCO; c++) {
        float xv = xs[c * 64 + kk];
        const float4* wr = (const float4*)(g_wct + c * NCO + og * 32);
#pragma unroll
        for (int i4 = 0; i4 < 8; i4++) {
            float4 wv = __ldg(wr + i4);
            acc[i4 * 4 + 0] = fmaf(wv.x, xv, acc[i4 * 4 + 0]);
            acc[i4 * 4 + 1] = fmaf(wv.y, xv, acc[i4 * 4 + 1]);
            acc[i4 * 4 + 2] = fmaf(wv.z, xv, acc[i4 * 4 + 2]);
            acc[i4 * 4 + 3] = fmaf(wv.w, xv, acc[i4 * 4 + 3]);
        }
    }
#pragma unroll
    for (int i = 0; i < 32; i++) {
        int o = og * 32 + i;
        g_zz[((b << 7) + o) * NH + k0 + kk] = acc[i] + g_bcv[o];
    }
}

// ---------------- 7: S = xn^T xn / sqrt(C)  [b,h,k] -------------------------
__global__ void __launch_bounds__(256) k_sgemm() {
    __shared__ float As[64 * 64], Bs[64 * 64];
    int k0 = blockIdx.x * 64, h0 = blockIdx.y * 64, b = blockIdx.z;
    int t = threadIdx.x, tx = t & 15, ty = t >> 4;
    float acc[4][4];
#pragma unroll
    for (int i = 0; i < 4; i++)
#pragma unroll
        for (int j = 0; j < 4; j++) acc[i][j] = 0.f;
    for (int cc = 0; cc < 2; ++cc) {
        int c0 = cc * 64;
        for (int i = t; i < 4096; i += 256) {
            int c = i >> 6, j = i & 63;
            As[i] = g_xn[((b << 7) + c0 + c) * NH + h0 + j];
            Bs[i] = g_xn[((b << 7) + c0 + c) * NH + k0 + j];
        }
        __syncthreads();
#pragma unroll 8
        for (int c = 0; c < 64; c++) {
            float4 av = *(const float4*)&As[c * 64 + ty * 4];
            float4 bv = *(const float4*)&Bs[c * 64 + tx * 4];
            float a[4] = {av.x, av.y, av.z, av.w};
            float bb[4] = {bv.x, bv.y, bv.z, bv.w};
#pragma unroll
            for (int i = 0; i < 4; i++)
#pragma unroll
                for (int j = 0; j < 4; j++) acc[i][j] = fmaf(a[i], bb[j], acc[i][j]);
        }
        __syncthreads();
    }
    const float SC = 0.08838834764831845f;  // 1/sqrt(128)
#pragma unroll
    for (int i = 0; i < 4; i++) {
        float4 v;
        v.x = acc[i][0] * SC; v.y = acc[i][1] * SC;
        v.z = acc[i][2] * SC; v.w = acc[i][3] * SC;
        *(float4*)&g_f[((size_t)(b << 9) + h0 + ty * 4 + i) * NH + k0 + tx * 4] = v;
    }
}

// ---------------- 8: row softmax over k (512) -------------------------------
__global__ void __launch_bounds__(128) k_softmax() {
    size_t row = blockIdx.x;
    float4* p = (float4*)(g_f + row * NH);
    int t = threadIdx.x, lane = t & 31, wid = t >> 5;
    __shared__ float sb[4];
    float4 v = p[t];
    float m = fmaxf(fmaxf(v.x, v.y), fmaxf(v.z, v.w));
    m = warpmax(m);
    if (lane == 0) sb[wid] = m;
    __syncthreads();
    m = fmaxf(fmaxf(sb[0], sb[1]), fmaxf(sb[2], sb[3]));
    float e0 = expf(v.x - m), e1 = expf(v.y - m), e2 = expf(v.z - m), e3 = expf(v.w - m);
    float s = e0 + e1 + e2 + e3;
    s = warpsum(s);
    __syncthreads();
    if (lane == 0) sb[wid] = s;
    __syncthreads();
    float inv = 1.f / (sb[0] + sb[1] + sb[2] + sb[3]);
    float4 o; o.x = e0 * inv; o.y = e1 * inv; o.z = e2 * inv; o.w = e3 * inv;
    p[t] = o;
}

// ---------------- 9: y3[b,o,h] = Σk f[b,h,k] z[b,o,k] + out_b[o] ------------
__global__ void __launch_bounds__(256) k_y3(const float* __restrict__ outb) {
    __shared__ float fs[64 * 35];
    __shared__ float zs[NCO * 32];
    int h0 = blockIdx.x * 64, b = blockIdx.y;
    int t = threadIdx.x, hx = t & 15, og = t >> 4;
    float acc[4][8];
#pragma unroll
    for (int j = 0; j < 4; j++)
#pragma unroll
        for (int i = 0; i < 8; i++) acc[j][i] = 0.f;
    for (int kt = 0; kt < 16; ++kt) {
        int k0 = kt * 32;
        for (int i = t; i < 2048; i += 256) {
            int hh = i >> 5, kk = i & 31;
            fs[hh * 35 + kk] = g_f[((size_t)(b << 9) + h0 + hh) * NH + k0 + kk];
        }
        for (int i = t; i < 4096; i += 256) {
            int o = i >> 5, kk = i & 31;
            zs[i] = g_zz[((b << 7) + o) * NH + k0 + kk];
        }
        __syncthreads();
#pragma unroll 4
        for (int kk = 0; kk < 32; kk++) {
            float fv[4], zv[8];
#pragma unroll
            for (int j = 0; j < 4; j++) fv[j] = fs[(hx * 4 + j) * 35 + kk];
#pragma unroll
            for (int i = 0; i < 8; i++) zv[i] = zs[(og * 8 + i) * 32 + kk];
#pragma unroll
            for (int j = 0; j < 4; j++)
#pragma unroll
                for (int i = 0; i < 8; i++) acc[j][i] = fmaf(fv[j], zv[i], acc[j][i]);
        }
        __syncthreads();
    }
#pragma unroll
    for (int i = 0; i < 8; i++) {
        int o = og * 8 + i;
        float ob = outb[o];
#pragma unroll
        for (int j = 0; j < 4; j++)
            g_y3[((b << 7) + o) * NH + h0 + hx * 4 + j] = acc[j][i] + ob;
    }
}

// ---------------- 10: BN2 stats from small tensors --------------------------
__global__ void __launch_bounds__(256) k_bn2red(const float* __restrict__ g2,
                                                const float* __restrict__ b2p) {
    int c = blockIdx.x;
    int t = threadIdx.x, lane = t & 31, wid = t >> 5;
    float sy = 0.f, sy2 = 0.f, sxy = 0.f;
    for (int i = t; i < NB * NH; i += 256) {
        int b = i >> 9, h = i & 511;
        size_t idx = (size_t)((b << 7) + c) * NH + h;
        float y = g_y3[idx], xm = g_xm[idx];
        sy += y; sy2 += y * y; sxy += y * xm;
    }
    float sp1 = 0.f, sp2 = 0.f;
    if (t < NB) { sp1 = g_p1[t * NCO + c]; sp2 = g_p2[t * NCO + c]; }
    __shared__ float rb[5][8];
    sy = warpsum(sy); sy2 = warpsum(sy2); sxy = warpsum(sxy);
    sp1 = warpsum(sp1); sp2 = warpsum(sp2);
    if (lane == 0) { rb[0][wid]=sy; rb[1][wid]=sy2; rb[2][wid]=sxy; rb[3][wid]=sp1; rb[4][wid]=sp2; }
    __syncthreads();
    if (t == 0) {
        float SY=0, SY2=0, SXY=0, P1=0, P2=0;
#pragma unroll
        for (int i = 0; i < 8; i++) { SY+=rb[0][i]; SY2+=rb[1][i]; SXY+=rb[2][i]; P1+=rb[3][i]; P2+=rb[4][i]; }
        float S1 = P1 + 64.f * SY;
        float S2 = P2 + 128.f * SXY + 64.f * SY2;
        float mean = S1 * (1.f / NHW_F);
        float var  = S2 * (1.f / NHW_F) - mean * mean;
        float a = g2[c] * rsqrtf(var + CEPS);
        g_a2[c] = a;
        g_b2v[c] = b2p[c] - mean * a;
    }
}

// ---------------- 11: fused epilogue: BN1+ReLU + add y + BN2 + SiLU ---------
__global__ void __launch_bounds__(256) k_final(float* __restrict__ out) {
    size_t gi = (size_t)blockIdx.x * 256 + threadIdx.x;
    size_t base = gi * 4;
    size_t row = base >> 6;
    int c = (int)((row >> 9) & 127);
    float a1 = g_a1[c], b1 = g_b1v[c], a2 = g_a2[c], b2 = g_b2v[c];
    float yv = g_y3[row];
    float4 v = *(const float4*)(g_hraw + base);
    float q, r[4], in[4] = {v.x, v.y, v.z, v.w};
#pragma unroll
    for (int i = 0; i < 4; i++) {
        float hp = fmaxf(fmaf(in[i], a1, b1), 0.f);
        q = fmaf(hp + yv, a2, b2);
        r[i] = q * (1.f / (1.f + expf(-q)));
    }
    float4 o; o.x = r[0]; o.y = r[1]; o.z = r[2]; o.w = r[3];
    *(float4*)(out + base) = o;
}

// ---------------- launch ----------------------------------------------------
extern "C" void kernel_launch(void* const* d_in, const int* in_sizes, int n_in,
                              void* d_out, int out_size) {
    const float* x      = (const float*)d_in[0];
    const float* conv_w = (const float*)d_in[1];
    const float* bn1_g  = (const float*)d_in[2];
    const float* bn1_b  = (const float*)d_in[3];
    const float* gw     = (const float*)d_in[4];
    const float* gb     = (const float*)d_in[5];
    const float* ow     = (const float*)d_in[6];
    const float* ob     = (const float*)d_in[7];
    const float* bn2_g  = (const float*)d_in[8];
    const float* bn2_b  = (const float*)d_in[9];
    float* out = (float*)d_out;

    static int smem_set = 0;
    if (!smem_set) {
        cudaFuncSetAttribute(k_conv_mma, cudaFuncAttributeMaxDynamicSharedMemorySize, SMEM_TC);
        smem_set = 1;
    }

    k_zero<<<1, 256>>>();
    k_wprep<<<9, 256>>>(conv_w);
    k_conv_mma<<<dim3(NH / 2, NB), 256, SMEM_TC>>>(x);
    k_bn1fin<<<1, 128>>>(bn1_g, bn1_b);
    k_bnrelu_xm<<<NB * NCO, 256>>>();
    k_ln<<<NB, 256>>>();
    k_wc<<<NCO, NCO>>>(ow, gw, gb);
    k_z<<<dim3(8, NB), 256>>>();
    k_sgemm<<<dim3(8, 8, NB), 256>>>();
    k_softmax<<<NB * NH, 128>>>();
    k_y3<<<dim3(8, NB), 256>>>(ob);
    k_bn2red<<<NCO, 256>>>(bn2_g, bn2_b);
    k_final<<<65536, 256>>>(out);
}

// round 14
// speedup vs baseline: 1.4732x; 1.1325x over previous
#include <cuda_runtime.h>
#include <cuda_bf16.h>
#include <cuda_fp16.h>
#include <cstdint>

#define NB 16
#define NCI 64
#define NCO 128
#define NH 512
#define NW 64
#define CEPS 1e-5f
#define NHW_F 524288.0f   // NB*NH*NW per-channel count

// ---------------- scratch (device globals; no allocations allowed) ----------
__device__ __half g_hraw[(size_t)NB * NCO * NH * NW];  // raw conv output fp16, 134MB
__device__ float g_xm[NB * NCO * NH];                  // row means of post-BN1-ReLU
__device__ float g_xn[NB * NCO * NH];                  // layernormed
__device__ float g_f[(size_t)NB * NH * NH];            // softmax(attention)
__device__ float g_zz[NB * NCO * NH];                  // z = Wc @ xn + bc
__device__ float g_y3[NB * NCO * NH];                  // final NL branch
__device__ float g_p1[NB * NCO];                       // per-(b,c) sum of hpost
__device__ float g_p2[NB * NCO];                       // per-(b,c) sum of hpost^2
__device__ float g_s1[NCO];                            // per-channel raw conv sums
__device__ float g_s2[NCO];
__device__ float g_a1[NCO], g_b1v[NCO];                // BN1 scale/shift
__device__ float g_a2[NCO], g_b2v[NCO];                // BN2 scale/shift
__device__ float g_wct[NCO * NCO];                     // (out_w@g_w) transposed [c][o]
__device__ float g_bcv[NCO];                           // out_w@g_b
// fp16 conv weights, pre-swizzled: per chunk (kh*3+kw), tile [co(128) x ci(64)]
__device__ __half g_wA[9 * 8192];

__device__ __forceinline__ float warpsum(float v) {
#pragma unroll
    for (int o = 16; o; o >>= 1) v += __shfl_down_sync(0xffffffffu, v, o);
    return v;
}
__device__ __forceinline__ float warpmax(float v) {
#pragma unroll
    for (int o = 16; o; o >>= 1) v = fmaxf(v, __shfl_xor_sync(0xffffffffu, v, o));
    return v;
}

// =================== mma.sync helpers (baseline PTX, compute_103-safe) ======
__device__ __forceinline__ uint32_t smem_u32(const void* p) {
    uint32_t a;
    asm("{ .reg .u64 t; cvta.to.shared.u64 t, %1; cvt.u32.u64 %0, t; }"
        : "=r"(a) : "l"(p));
    return a;
}
__device__ __forceinline__ void ldsm4(uint32_t* r, uint32_t a) {
    asm volatile("ldmatrix.sync.aligned.m8n8.x4.shared.b16 {%0,%1,%2,%3}, [%4];"
                 : "=r"(r[0]), "=r"(r[1]), "=r"(r[2]), "=r"(r[3]) : "r"(a));
}
__device__ __forceinline__ void mma16816h(float* d, const uint32_t* a, const uint32_t* b) {
    asm volatile("mma.sync.aligned.m16n8k16.row.col.f32.f16.f16.f32 "
                 "{%0,%1,%2,%3}, {%4,%5,%6,%7}, {%8,%9}, {%0,%1,%2,%3};"
                 : "+f"(d[0]), "+f"(d[1]), "+f"(d[2]), "+f"(d[3])
                 : "r"(a[0]), "r"(a[1]), "r"(a[2]), "r"(a[3]),
                   "r"(b[0]), "r"(b[1]));
}
__device__ __forceinline__ void cp16(uint32_t s, const void* g) {
    asm volatile("cp.async.cg.shared.global [%0], [%1], 16;" :: "r"(s), "l"(g));
}
#define CP_COMMIT() asm volatile("cp.async.commit_group;" ::: "memory")
#define CP_WAIT0()  asm volatile("cp.async.wait_group 0;" ::: "memory")

// A tile: rows of 64 fp16 (128B), 16B chunks XOR-swizzled by row&7
__device__ __forceinline__ uint32_t tile_addr(uint32_t base, int row, int kc) {
    return base + row * 128 + ((kc ^ (row & 7)) << 4);
}
// A-operand x4 at (m0, kc16Bchunk)
__device__ __forceinline__ void ld_a(uint32_t* r, uint32_t base, int m0, int kc, int lane) {
    int sel = lane >> 3;
    int rr = m0 + (lane & 7) + ((sel & 1) << 3);
    int cc = kc + (sel >> 1);
    ldsm4(r, tile_addr(base, rr, cc));
}
// B-operand from the extended input tile: pixel n -> (hrow=r+kh, wext=w+kw)
// ext layout: [(hrow*66+wext)][64 ci fp16 = 128B], chunk XOR-swizzled by wext&7
__device__ __forceinline__ void ld_b_ext(uint32_t* r, uint32_t base, int n0, int kc,
                                         int kh, int kw, int lane) {
    int sel = lane >> 3;
    int n = n0 + (lane & 7) + ((sel >> 1) << 3);
    int cc = kc + (sel & 1);
    int hrow = (n >> 6) + kh;
    int wext = (n & 63) + kw;
    uint32_t addr = base + (uint32_t)(hrow * 66 + wext) * 128
                  + (((uint32_t)cc ^ (uint32_t)(wext & 7)) << 4);
    ldsm4(r, addr);
}

// smem layout for conv kernel (dynamic): double-buffered A + single fp16 ext.
// After the mainloop the whole buffer is reused as the repack staging area:
// half out[128 co][pitch 136 halves] = 34816 B  (< SMEM_TC).
#define OFF_A0 0
#define OFF_A1 16384
#define OFF_E  32768
#define EXT_PITCH 8448              // 66 * 128 bytes per h-row
#define SMEM_TC (OFF_E + 4 * EXT_PITCH)   // 66560 (65KB)
#define RP_PITCH 136                // repack pitch in halves (68 words, bank-stride 4)

// ---------------- 0: zero the atomic accumulators ---------------------------
__global__ void k_zero() {
    int t = threadIdx.x;
    if (t < NCO) { g_s1[t] = 0.f; g_s2[t] = 0.f; }
}

// ---------------- 0b: weight prep: fp16, pre-swizzled ------------------------
__global__ void k_wprep(const float* __restrict__ cw) {
    int c9 = blockIdx.x;
    int kh = c9 / 3, kw = c9 % 3;
    for (int i = threadIdx.x; i < 8192; i += 256) {
        int co = i >> 6, ci = i & 63;
        float v = cw[co * 576 + ci * 9 + kh * 3 + kw];
        uint32_t off = (uint32_t)co * 128 + ((((uint32_t)ci >> 3) ^ (co & 7)) << 4)
                     + (ci & 7) * 2;                       // bytes
        g_wA[c9 * 8192 + (off >> 1)] = __float2half(v);
    }
}

// ---------------- 1: conv 3x3 reflect via mma.sync fp16 ---------------------
// grid (256 h-pairs, 16 b), 256 threads = 8 warps (4m x 2n).
// CTA tile: [128 co] x [128 px = 2 h-rows x 64 w]; K = 9 chunks of 64 ci.
// Epilogue: round to fp16, stats from rounded, smem repack -> coalesced stores.
__global__ void __launch_bounds__(256) k_conv_mma(const float* __restrict__ x) {
    extern __shared__ char smem[];
    uint32_t sb = smem_u32(smem);
    int t = threadIdx.x, wid = t >> 5, lane = t & 31;
    int h0 = blockIdx.x * 2, b = blockIdx.y;
    int wm = (wid & 3) * 32;      // warp m-base (couts)
    int wn = (wid >> 2) * 64;     // warp n-base (pixels)

    float d[2][8][4];
#pragma unroll
    for (int i = 0; i < 2; i++)
#pragma unroll
        for (int j = 0; j < 8; j++)
#pragma unroll
            for (int q = 0; q < 4; q++) d[i][j][q] = 0.f;

    const float* xb = x + (size_t)b * NCI * NH * NW;

    // ---- prologue: async stage A[0] while we build the ext tile ------------
    {
        const char* src = (const char*)(g_wA + 0);
        for (int i = t; i < 1024; i += 256)
            cp16(sb + OFF_A0 + i * 16, src + i * 16);
        CP_COMMIT();
    }

    // ---- build extended input tile: (hrow 0..3, ci 0..63, wext 0..65) ------
    for (int p = wid; p < 256; p += 8) {
        int hrow = p >> 6, ci = p & 63;
        int row = h0 + hrow - 1;
        row = (row < 0) ? 1 : ((row > NH - 1) ? NH - 2 : row);
        const float* xr = xb + ((size_t)ci * NH + row) * NW;
        uint32_t rowoff = (uint32_t)(hrow * 66) * 128;
        int ci8 = ci >> 3, cib = (ci & 7) * 2;
#pragma unroll
        for (int rep = 0; rep < 3; rep++) {
            int wext = lane + rep * 32;
            if (rep == 2 && lane >= 2) break;
            if (rep == 2) wext = 64 + lane;
            int ws = wext - 1;
            ws = (ws < 0) ? 1 : ((ws > NW - 1) ? NW - 2 : ws);
            float v = xr[ws];
            uint32_t off = rowoff + (uint32_t)wext * 128
                         + (((uint32_t)ci8 ^ (uint32_t)(wext & 7)) << 4) + cib;
            *(__half*)(smem + OFF_E + off) = __float2half(v);
        }
    }

    // ---- mainloop over 9 (kh,kw) chunks, A double-buffered -----------------
    for (int c9 = 0; c9 < 9; ++c9) {
        int kh = c9 / 3, kw = c9 - kh * 3;
        uint32_t abase = sb + ((c9 & 1) ? OFF_A1 : OFF_A0);
        CP_WAIT0();          // A[c9] arrived (only outstanding group)
        __syncthreads();     // + ext visible (first iter); all warps past c9-1
        if (c9 < 8) {        // prefetch A[c9+1] into the other buffer
            uint32_t nb = sb + (((c9 + 1) & 1) ? OFF_A1 : OFF_A0);
            const char* src = (const char*)(g_wA + (c9 + 1) * 8192);
            for (int i = t; i < 1024; i += 256)
                cp16(nb + i * 16, src + i * 16);
            CP_COMMIT();
        }
#pragma unroll
        for (int ks = 0; ks < 4; ks++) {
            int kc = ks * 2;
            uint32_t ah[2][4];
            ld_a(ah[0], abase, wm,      kc, lane);
            ld_a(ah[1], abase, wm + 16, kc, lane);
#pragma unroll
            for (int j = 0; j < 4; j++) {
                uint32_t bh[4];
                ld_b_ext(bh, sb + OFF_E, wn + j * 16, kc, kh, kw, lane);
#pragma unroll
                for (int mf = 0; mf < 2; mf++) {
                    mma16816h(d[mf][2 * j],     ah[mf], bh);
                    mma16816h(d[mf][2 * j + 1], ah[mf], bh + 2);
                }
            }
        }
    }

    // ---- epilogue: round to fp16, stats, smem repack, coalesced stores -----
    CP_WAIT0();
    __syncthreads();   // everyone done reading ext/A tiles before reuse
    float s1a[4] = {0.f, 0.f, 0.f, 0.f}, s2a[4] = {0.f, 0.f, 0.f, 0.f};
#pragma unroll
    for (int mf = 0; mf < 2; mf++)
#pragma unroll
        for (int half = 0; half < 2; half++) {
            int co = wm + mf * 16 + (lane >> 2) + half * 8;
            int slot = mf * 2 + half;
#pragma unroll
            for (int nf = 0; nf < 8; nf++) {
                int n = wn + nf * 8 + (lane & 3) * 2;
                __half2 st = __floats2half2_rn(d[mf][nf][half * 2 + 0],
                                               d[mf][nf][half * 2 + 1]);
                *(__half2*)(smem + (uint32_t)co * (RP_PITCH * 2) + (uint32_t)n * 2) = st;
                float r0 = __half2float(__low2half(st));
                float r1 = __half2float(__high2half(st));
                s1a[slot] += r0 + r1;
                s2a[slot] += r0 * r0 + r1 * r1;
            }
        }
    __syncthreads();
    // coalesced 128B-row stores: (co, r) row = 64 halves = 8 uint4
    for (int i = t; i < 2048; i += 256) {
        int co = i >> 4, rw = (i >> 3) & 1, q = i & 7;
        uint4 v = *(const uint4*)(smem + (uint32_t)co * (RP_PITCH * 2)
                                  + (uint32_t)(rw * 64 + q * 8) * 2);
        *(uint4*)&g_hraw[((size_t)(b * NCO + co) * NH + h0 + rw) * NW + q * 8] = v;
    }
#pragma unroll
    for (int s = 0; s < 4; s++) {
        s1a[s] += __shfl_xor_sync(0xffffffffu, s1a[s], 1);
        s1a[s] += __shfl_xor_sync(0xffffffffu, s1a[s], 2);
        s2a[s] += __shfl_xor_sync(0xffffffffu, s2a[s], 1);
        s2a[s] += __shfl_xor_sync(0xffffffffu, s2a[s], 2);
    }
    if ((lane & 3) == 0) {
#pragma unroll
        for (int s = 0; s < 4; s++) {
            int co = wm + (s >> 1) * 16 + (lane >> 2) + (s & 1) * 8;
            atomicAdd(&g_s1[co], s1a[s]);
            atomicAdd(&g_s2[co], s2a[s]);
        }
    }
}

// ---------------- 2: finalize BN1 scale/shift -------------------------------
__global__ void k_bn1fin(const float* __restrict__ g1, const float* __restrict__ b1) {
    int c = threadIdx.x;
    if (c < NCO) {
        float mean = g_s1[c] * (1.f / NHW_F);
        float var  = g_s2[c] * (1.f / NHW_F) - mean * mean;
        float a = g1[c] * rsqrtf(var + CEPS);
        g_a1[c] = a;
        g_b1v[c] = b1[c] - mean * a;
    }
}

// ---------------- 3: apply BN1+ReLU, row means over W, Σh/Σh² partials ------
// grid: 2048 = (b,c). 256 threads; octet of lanes per h-row (uint4 = 8 halves),
// 16 independent iterations -> high MLP, 3 shfls per row-sum. Reads coalesced.
__global__ void __launch_bounds__(256) k_bnrelu_xm() {
    int bc = blockIdx.x;
    int c = bc & 127;
    int t = threadIdx.x, lane = t & 31, wid = t >> 5;
    float a1 = g_a1[c], b1 = g_b1v[c];
    const uint4* src = (const uint4*)(g_hraw + (size_t)bc * NH * NW); // 8 uint4/row
    float p1 = 0.f, p2 = 0.f;
#pragma unroll 4
    for (int it = 0; it < 16; ++it) {
        int row = it * 32 + wid * 4 + (lane >> 3);
        uint4 u = src[row * 8 + (lane & 7)];
        float s = 0.f;
        uint32_t uu[4] = {u.x, u.y, u.z, u.w};
#pragma unroll
        for (int q = 0; q < 4; q++) {
            float2 f = __half22float2(*(__half2*)&uu[q]);
            float v0 = fmaxf(fmaf(f.x, a1, b1), 0.f);
            float v1 = fmaxf(fmaf(f.y, a1, b1), 0.f);
            s += v0 + v1;
            p2 += v0 * v0 + v1 * v1;
        }
        p1 += s;
        s += __shfl_xor_sync(0xffffffffu, s, 1);
        s += __shfl_xor_sync(0xffffffffu, s, 2);
        s += __shfl_xor_sync(0xffffffffu, s, 4);
        if ((lane & 7) == 0) g_xm[(size_t)bc * NH + row] = s * (1.f / 64.f);
    }
    __shared__ float r1[8], r2[8];
    p1 = warpsum(p1); p2 = warpsum(p2);
    if (lane == 0) { r1[wid] = p1; r2[wid] = p2; }
    __syncthreads();
    if (t == 0) {
        float a = 0.f, b2 = 0.f;
#pragma unroll
        for (int i = 0; i < 8; i++) { a += r1[i]; b2 += r2[i]; }
        g_p1[bc] = a; g_p2[bc] = b2;
    }
}

// ---------------- 4: layernorm over (C,H) per batch -------------------------
__global__ void __launch_bounds__(256) k_ln() {
    int b = blockIdx.x;
    const float* xm = g_xm + b * (NCO * NH);
    float* xn = g_xn + b * (NCO * NH);
    int t = threadIdx.x, lane = t & 31, wid = t >> 5;
    float s = 0.f, s2 = 0.f;
    for (int i = t; i < NCO * NH; i += 256) { float v = xm[i]; s += v; s2 += v * v; }
    __shared__ float rb[16];
    __shared__ float st[2];
    s = warpsum(s); s2 = warpsum(s2);
    if (lane == 0) { rb[wid] = s; rb[8 + wid] = s2; }
    __syncthreads();
    if (t == 0) {
        float a = 0.f, b2 = 0.f;
#pragma unroll
        for (int i = 0; i < 8; i++) { a += rb[i]; b2 += rb[8 + i]; }
        float mu = a * (1.f / 65536.f);
        float var = b2 * (1.f / 65536.f) - mu * mu;
        st[0] = mu; st[1] = rsqrtf(var + CEPS);
    }
    __syncthreads();
    float mu = st[0], rs = st[1];
    for (int i = t; i < NCO * NH; i += 256) xn[i] = (xm[i] - mu) * rs;
}

// ---------------- 5: Wc = out_w @ g_w (stored transposed), bc = out_w @ g_b -
__global__ void k_wc(const float* __restrict__ ow, const float* __restrict__ gw,
                     const float* __restrict__ gb) {
    int o = blockIdx.x, c = threadIdx.x;
    float s = 0.f;
    for (int m = 0; m < NCO; m++) s = fmaf(ow[o * NCO + m], gw[m * NCO + c], s);
    g_wct[c * NCO + o] = s;
    if (c == 0) {
        float bb = 0.f;
        for (int m = 0; m < NCO; m++) bb = fmaf(ow[o * NCO + m], gb[m], bb);
        g_bcv[o] = bb;
    }
}

// ---------------- 6: z[b,o,k] = Σc Wc[o,c]*xn[b,c,k] + bc[o] ----------------
__global__ void __launch_bounds__(256) k_z() {
    __shared__ float xs[NCO * 64];
    int k0 = blockIdx.x * 64, b = blockIdx.y;
    int t = threadIdx.x;
    for (int i = t; i < NCO * 64; i += 256) {
        int c = i >> 6, kk = i & 63;
        xs[i] = g_xn[((b << 7) + c) * NH + k0 + kk];
    }
    __syncthreads();
    int kk = t & 63, og = t >> 6;
    float acc[32];
#pragma unroll
    for (int i = 0; i < 32; i++) acc[i] = 0.f;
    for (int c = 0; c < NCO; c++) {
        float xv = xs[c * 64 + kk];
        const float4* wr = (const float4*)(g_wct + c * NCO + og * 32);
#pragma unroll
        for (int i4 = 0; i4 < 8; i4++) {
            float4 wv = __ldg(wr + i4);
            acc[i4 * 4 + 0] = fmaf(wv.x, xv, acc[i4 * 4 + 0]);
            acc[i4 * 4 + 1] = fmaf(wv.y, xv, acc[i4 * 4 + 1]);
            acc[i4 * 4 + 2] = fmaf(wv.z, xv, acc[i4 * 4 + 2]);
            acc[i4 * 4 + 3] = fmaf(wv.w, xv, acc[i4 * 4 + 3]);
        }
    }
#pragma unroll
    for (int i = 0; i < 32; i++) {
        int o = og * 32 + i;
        g_zz[((b << 7) + o) * NH + k0 + kk] = acc[i] + g_bcv[o];
    }
}

// ---------------- 7: S = xn^T xn / sqrt(C)  [b,h,k] -------------------------
__global__ void __launch_bounds__(256) k_sgemm() {
    __shared__ float As[64 * 64], Bs[64 * 64];
    int k0 = blockIdx.x * 64, h0 = blockIdx.y * 64, b = blockIdx.z;
    int t = threadIdx.x, tx = t & 15, ty = t >> 4;
    float acc[4][4];
#pragma unroll
    for (int i = 0; i < 4; i++)
#pragma unroll
        for (int j = 0; j < 4; j++) acc[i][j] = 0.f;
    for (int cc = 0; cc < 2; ++cc) {
        int c0 = cc * 64;
        for (int i = t; i < 4096; i += 256) {
            int c = i >> 6, j = i & 63;
            As[i] = g_xn[((b << 7) + c0 + c) * NH + h0 + j];
            Bs[i] = g_xn[((b << 7) + c0 + c) * NH + k0 + j];
        }
        __syncthreads();
#pragma unroll 8
        for (int c = 0; c < 64; c++) {
            float4 av = *(const float4*)&As[c * 64 + ty * 4];
            float4 bv = *(const float4*)&Bs[c * 64 + tx * 4];
            float a[4] = {av.x, av.y, av.z, av.w};
            float bb[4] = {bv.x, bv.y, bv.z, bv.w};
#pragma unroll
            for (int i = 0; i < 4; i++)
#pragma unroll
                for (int j = 0; j < 4; j++) acc[i][j] = fmaf(a[i], bb[j], acc[i][j]);
        }
        __syncthreads();
    }
    const float SC = 0.08838834764831845f;  // 1/sqrt(128)
#pragma unroll
    for (int i = 0; i < 4; i++) {
        float4 v;
        v.x = acc[i][0] * SC; v.y = acc[i][1] * SC;
        v.z = acc[i][2] * SC; v.w = acc[i][3] * SC;
        *(float4*)&g_f[((size_t)(b << 9) + h0 + ty * 4 + i) * NH + k0 + tx * 4] = v;
    }
}

// ---------------- 8: row softmax over k (512) -------------------------------
__global__ void __launch_bounds__(128) k_softmax() {
    size_t row = blockIdx.x;
    float4* p = (float4*)(g_f + row * NH);
    int t = threadIdx.x, lane = t & 31, wid = t >> 5;
    __shared__ float sb[4];
    float4 v = p[t];
    float m = fmaxf(fmaxf(v.x, v.y), fmaxf(v.z, v.w));
    m = warpmax(m);
    if (lane == 0) sb[wid] = m;
    __syncthreads();
    m = fmaxf(fmaxf(sb[0], sb[1]), fmaxf(sb[2], sb[3]));
    float e0 = expf(v.x - m), e1 = expf(v.y - m), e2 = expf(v.z - m), e3 = expf(v.w - m);
    float s = e0 + e1 + e2 + e3;
    s = warpsum(s);
    __syncthreads();
    if (lane == 0) sb[wid] = s;
    __syncthreads();
    float inv = 1.f / (sb[0] + sb[1] + sb[2] + sb[3]);
    float4 o; o.x = e0 * inv; o.y = e1 * inv; o.z = e2 * inv; o.w = e3 * inv;
    p[t] = o;
}

// ---------------- 9: y3[b,o,h] = Σk f[b,h,k] z[b,o,k] + out_b[o] ------------
__global__ void __launch_bounds__(256) k_y3(const float* __restrict__ outb) {
    __shared__ float fs[64 * 35];
    __shared__ float zs[NCO * 32];
    int h0 = blockIdx.x * 64, b = blockIdx.y;
    int t = threadIdx.x, hx = t & 15, og = t >> 4;
    float acc[4][8];
#pragma unroll
    for (int j = 0; j < 4; j++)
#pragma unroll
        for (int i = 0; i < 8; i++) acc[j][i] = 0.f;
    for (int kt = 0; kt < 16; ++kt) {
        int k0 = kt * 32;
        for (int i = t; i < 2048; i += 256) {
            int hh = i >> 5, kk = i & 31;
            fs[hh * 35 + kk] = g_f[((size_t)(b << 9) + h0 + hh) * NH + k0 + kk];
        }
        for (int i = t; i < 4096; i += 256) {
            int o = i >> 5, kk = i & 31;
            zs[i] = g_zz[((b << 7) + o) * NH + k0 + kk];
        }
        __syncthreads();
#pragma unroll 4
        for (int kk = 0; kk < 32; kk++) {
            float fv[4], zv[8];
#pragma unroll
            for (int j = 0; j < 4; j++) fv[j] = fs[(hx * 4 + j) * 35 + kk];
#pragma unroll
            for (int i = 0; i < 8; i++) zv[i] = zs[(og * 8 + i) * 32 + kk];
#pragma unroll
            for (int j = 0; j < 4; j++)
#pragma unroll
                for (int i = 0; i < 8; i++) acc[j][i] = fmaf(fv[j], zv[i], acc[j][i]);
        }
        __syncthreads();
    }
#pragma unroll
    for (int i = 0; i < 8; i++) {
        int o = og * 8 + i;
        float ob = outb[o];
#pragma unroll
        for (int j = 0; j < 4; j++)
            g_y3[((b << 7) + o) * NH + h0 + hx * 4 + j] = acc[j][i] + ob;
    }
}

// ---------------- 10: BN2 stats from small tensors --------------------------
__global__ void __launch_bounds__(256) k_bn2red(const float* __restrict__ g2,
                                                const float* __restrict__ b2p) {
    int c = blockIdx.x;
    int t = threadIdx.x, lane = t & 31, wid = t >> 5;
    float sy = 0.f, sy2 = 0.f, sxy = 0.f;
    for (int i = t; i < NB * NH; i += 256) {
        int b = i >> 9, h = i & 511;
        size_t idx = (size_t)((b << 7) + c) * NH + h;
        float y = g_y3[idx], xm = g_xm[idx];
        sy += y; sy2 += y * y; sxy += y * xm;
    }
    float sp1 = 0.f, sp2 = 0.f;
    if (t < NB) { sp1 = g_p1[t * NCO + c]; sp2 = g_p2[t * NCO + c]; }
    __shared__ float rb[5][8];
    sy = warpsum(sy); sy2 = warpsum(sy2); sxy = warpsum(sxy);
    sp1 = warpsum(sp1); sp2 = warpsum(sp2);
    if (lane == 0) { rb[0][wid]=sy; rb[1][wid]=sy2; rb[2][wid]=sxy; rb[3][wid]=sp1; rb[4][wid]=sp2; }
    __syncthreads();
    if (t == 0) {
        float SY=0, SY2=0, SXY=0, P1=0, P2=0;
#pragma unroll
        for (int i = 0; i < 8; i++) { SY+=rb[0][i]; SY2+=rb[1][i]; SXY+=rb[2][i]; P1+=rb[3][i]; P2+=rb[4][i]; }
        float S1 = P1 + 64.f * SY;
        float S2 = P2 + 128.f * SXY + 64.f * SY2;
        float mean = S1 * (1.f / NHW_F);
        float var  = S2 * (1.f / NHW_F) - mean * mean;
        float a = g2[c] * rsqrtf(var + CEPS);
        g_a2[c] = a;
        g_b2v[c] = b2p[c] - mean * a;
    }
}

// ---------------- 11: fused epilogue: BN1+ReLU + add y + BN2 + SiLU ---------
// 8 fp16 elems per thread (one coalesced uint4), all within one h-row.
__global__ void __launch_bounds__(256) k_final(float* __restrict__ out) {
    size_t gi = (size_t)blockIdx.x * 256 + threadIdx.x;
    size_t base = gi * 8;
    size_t row = base >> 6;                               // (b*128+c)*512+h
    int c = (int)((row >> 9) & 127);
    float a1 = g_a1[c], b1 = g_b1v[c], a2 = g_a2[c], b2 = g_b2v[c];
    float yv = g_y3[row];
    uint4 u = *(const uint4*)(g_hraw + base);
    uint32_t uu[4] = {u.x, u.y, u.z, u.w};
    float r[8];
#pragma unroll
    for (int q = 0; q < 4; q++) {
        float2 f = __half22float2(*(__half2*)&uu[q]);
        float hp0 = fmaxf(fmaf(f.x, a1, b1), 0.f);
        float hp1 = fmaxf(fmaf(f.y, a1, b1), 0.f);
        float q0 = fmaf(hp0 + yv, a2, b2);
        float q1 = fmaf(hp1 + yv, a2, b2);
        r[q * 2 + 0] = q0 * (1.f / (1.f + expf(-q0)));
        r[q * 2 + 1] = q1 * (1.f / (1.f + expf(-q1)));
    }
    float4 o0; o0.x = r[0]; o0.y = r[1]; o0.z = r[2]; o0.w = r[3];
    float4 o1; o1.x = r[4]; o1.y = r[5]; o1.z = r[6]; o1.w = r[7];
    *(float4*)(out + base) = o0;
    *(float4*)(out + base + 4) = o1;
}

// ---------------- launch ----------------------------------------------------
extern "C" void kernel_launch(void* const* d_in, const int* in_sizes, int n_in,
                              void* d_out, int out_size) {
    const float* x      = (const float*)d_in[0];
    const float* conv_w = (const float*)d_in[1];
    const float* bn1_g  = (const float*)d_in[2];
    const float* bn1_b  = (const float*)d_in[3];
    const float* gw     = (const float*)d_in[4];
    const float* gb     = (const float*)d_in[5];
    const float* ow     = (const float*)d_in[6];
    const float* ob     = (const float*)d_in[7];
    const float* bn2_g  = (const float*)d_in[8];
    const float* bn2_b  = (const float*)d_in[9];
    float* out = (float*)d_out;

    static int smem_set = 0;
    if (!smem_set) {
        cudaFuncSetAttribute(k_conv_mma, cudaFuncAttributeMaxDynamicSharedMemorySize, SMEM_TC);
        smem_set = 1;
    }

    k_zero<<<1, 256>>>();
    k_wprep<<<9, 256>>>(conv_w);
    k_conv_mma<<<dim3(NH / 2, NB), 256, SMEM_TC>>>(x);
    k_bn1fin<<<1, 128>>>(bn1_g, bn1_b);
    k_bnrelu_xm<<<NB * NCO, 256>>>();
    k_ln<<<NB, 256>>>();
    k_wc<<<NCO, NCO>>>(ow, gw, gb);
    k_z<<<dim3(8, NB), 256>>>();
    k_sgemm<<<dim3(8, 8, NB), 256>>>();
    k_softmax<<<NB * NH, 128>>>();
    k_y3<<<dim3(8, NB), 256>>>(ob);
    k_bn2red<<<NCO, 256>>>(bn2_g, bn2_b);
    k_final<<<65536 / 2, 256>>>(out);
}